// round 9
// baseline (speedup 1.0000x reference)
#include <cuda_runtime.h>
#include <cuda_fp16.h>
#include <cstdint>

// ===========================================================================
// SSRupsampling via HMMA (mma.sync m16n8k16, fp32 accum), fp16 3-product
// split. Conv B = shifted view of compact [pix,512] act (no im2col).
// GEMM: 128(M) x 256(N) block tile, 512 threads, 16 warps (4m x 4n),
// warp tile 32x64 (R5 register budget), 3-stage cp.async pipeline.
// Pixel shuffles fused into GEMM epilogues.
// ===========================================================================

// ------------------------------ scratch -----------------------------------
__device__ __half g_aHi[36864L * 512], g_aLo[36864L * 512];
__device__ __half g_bHi[36864L * 512], g_bLo[36864L * 512];
__device__ __half g_cHi[18432 * 512],  g_cLo[18432 * 512];
__device__ __half g_B2hi[9216 * 512],  g_B2lo[9216 * 512];
__device__ __half g_wch_hi[512 * 2048], g_wch_lo[512 * 2048];
__device__ __half g_ww_hi[1024 * 512],  g_ww_lo[1024 * 512];
__device__ __half g_wH_hi[1024 * 512],  g_wH_lo[1024 * 512];
__device__ __half g_wlr_hi[512 * 4608], g_wlr_lo[512 * 4608];
__device__ __half g_wdu_hi[512 * 4608], g_wdu_lo[512 * 4608];

// ------------------------------ helpers -----------------------------------
__device__ __forceinline__ uint32_t smem_u32(const void* p) {
    uint32_t a;
    asm("{ .reg .u64 t; cvta.to.shared.u64 t, %1; cvt.u32.u64 %0, t; }"
        : "=r"(a) : "l"(p));
    return a;
}
__device__ __forceinline__ void ldsm_x4(uint32_t* r, uint32_t addr) {
    asm volatile("ldmatrix.sync.aligned.m8n8.x4.shared.b16 {%0,%1,%2,%3}, [%4];"
                 : "=r"(r[0]), "=r"(r[1]), "=r"(r[2]), "=r"(r[3]) : "r"(addr));
}
__device__ __forceinline__ void mma16816(float* c, const uint32_t* a,
                                         const uint32_t* b) {
    asm volatile(
        "mma.sync.aligned.m16n8k16.row.col.f32.f16.f16.f32 "
        "{%0,%1,%2,%3}, {%4,%5,%6,%7}, {%8,%9}, {%0,%1,%2,%3};"
        : "+f"(c[0]), "+f"(c[1]), "+f"(c[2]), "+f"(c[3])
        : "r"(a[0]), "r"(a[1]), "r"(a[2]), "r"(a[3]), "r"(b[0]), "r"(b[1]));
}
__device__ __forceinline__ void cp16(uint32_t sa, const void* ga) {
    asm volatile("cp.async.cg.shared.global [%0], [%1], 16;"
                 :: "r"(sa), "l"(ga));
}
__device__ __forceinline__ void cp16p(uint32_t sa, const void* ga, int sz) {
    asm volatile("cp.async.cg.shared.global [%0], [%1], 16, %2;"
                 :: "r"(sa), "l"(ga), "r"(sz));
}

#define BK 32
#define PITCH 80
#define A_BYTES (128 * PITCH)      // 10240 per A half (hi or lo)
#define B_BYTES (256 * PITCH)      // 20480 per B half
#define OFF_AHI 0
#define OFF_ALO A_BYTES
#define OFF_BHI (2 * A_BYTES)
#define OFF_BLO (2 * A_BYTES + B_BYTES)
#define STAGE_BYTES (2 * A_BYTES + 2 * B_BYTES)   // 61440
#define NSTAGE 3
#define SMEM_TOTAL (NSTAGE * STAGE_BYTES)         // 184320

__device__ __forceinline__ void split_g(float v, __half* hi, __half* lo,
                                        long idx) {
    __half h = __float2half_rn(v);
    hi[idx] = h;
    lo[idx] = __float2half_rn(v - __half2float(h));
}

// ---------------------------------------------------------------------------
// GEMM: D[m,n] = sum_k A[m,k]*B[n,k], fp16 x3 split, fp32 accum.
// Block tile 128x256, BK=32, 512 threads (16 warps, 4m x 4n), warp 32x64.
// conv!=0: K=4608 logical (9 taps x 512); B read from [Npix,512] with row
// shift (t-4) and l/s boundary mask (pix = img*288 + l*3 + s).
// Modes: 1 split [pix,512]; 3 bias+relu split [pix,512];
//        4 bias+relu NCHW scatter (final); 5 split + H-shuffle (stage2);
//        6 split + W-shuffle (w_H stage).
// ---------------------------------------------------------------------------
__global__ __launch_bounds__(512, 1)
void gemm_hmma(const __half* __restrict__ Ahi, const __half* __restrict__ Alo,
               const __half* __restrict__ Bhi, const __half* __restrict__ Blo,
               int K, int Kb, int conv, int mode,
               const float* __restrict__ bias, float* __restrict__ outF,
               __half* __restrict__ outHi, __half* __restrict__ outLo) {
    extern __shared__ char smem[];
    const uint32_t sb = smem_u32(smem);
    const int tid = threadIdx.x;
    const int lane = tid & 31, wid = tid >> 5;
    const int wm = wid & 3, wn = wid >> 2;     // 4m x 4n warps
    const int m0 = blockIdx.x * 128;
    const long n0 = (long)blockIdx.y * 256;

    const __half* gA0 = Ahi + (long)m0 * K;
    const __half* gA1 = Alo + (long)m0 * K;
    const __half* gB0 = Bhi + n0 * Kb;
    const __half* gB1 = Blo + n0 * Kb;

    const int lrow = tid >> 2, lcol = tid & 3;   // A rows 0..127; B rows lrow, +128

    // conv B-row geometry (pix = img*288 + l*3 + s)
    int l0 = 0, s0 = 0, l1 = 0, s1 = 0;
    if (conv) {
        const int p0 = (int)n0 + lrow, p1 = p0 + 128;
        s0 = p0 % 3; l0 = (p0 / 3) % 96;
        s1 = p1 % 3; l1 = (p1 / 3) % 96;
    }

    const int lg = lane >> 3, lr = lane & 7;
    const uint32_t aoff = (uint32_t)(((lg & 1) * 8 + lr) + wm * 32) * PITCH +
                          (lg >> 1) * 16;
    const uint32_t boff = (uint32_t)(((lg >> 1) * 8 + lr) + wn * 64) * PITCH +
                          (lg & 1) * 16;

    float acc[2][8][4];
    #pragma unroll
    for (int i = 0; i < 2; i++)
        #pragma unroll
        for (int j = 0; j < 8; j++)
            #pragma unroll
            for (int c = 0; c < 4; c++) acc[i][j][c] = 0.f;

    const int nC = K / BK;

    auto issue = [&](int kc) {
        const uint32_t so = sb + (kc % NSTAGE) * STAGE_BYTES;
        // A: 128 rows x 4 cp16-cols; 512 threads -> 1 per half
        {
            const long kb = (long)kc * BK;
            const uint32_t sa = so + lrow * PITCH + lcol * 16;
            const long ga = (long)lrow * K + kb + lcol * 8;
            cp16(sa + OFF_AHI, gA0 + ga);
            cp16(sa + OFF_ALO, gA1 + ga);
        }
        // B: 256 rows; thread handles rows lrow and lrow+128
        const uint32_t s0a = so + lrow * PITCH + lcol * 16;
        const uint32_t s1a = so + (lrow + 128) * PITCH + lcol * 16;
        if (conv) {
            const int t = kc >> 4;                // tap 0..8
            const int dlm = t / 3 - 1, dsm = t % 3 - 1;
            const int koff = (kc & 15) * 32 + lcol * 8;
            const long rs = (long)(t - 4) * Kb;
            const int v0 = ((unsigned)(l0 + dlm) < 96u &&
                            (unsigned)(s0 + dsm) < 3u) ? 16 : 0;
            const int v1 = ((unsigned)(l1 + dlm) < 96u &&
                            (unsigned)(s1 + dsm) < 3u) ? 16 : 0;
            const long gb0 = (long)lrow * Kb + rs + koff;
            const long gb1 = (long)(lrow + 128) * Kb + rs + koff;
            cp16p(s0a + OFF_BHI, gB0 + gb0, v0);
            cp16p(s1a + OFF_BHI, gB0 + gb1, v1);
            cp16p(s0a + OFF_BLO, gB1 + gb0, v0);
            cp16p(s1a + OFF_BLO, gB1 + gb1, v1);
        } else {
            const long kb = (long)kc * BK;
            const long gb0 = (long)lrow * Kb + kb + lcol * 8;
            const long gb1 = (long)(lrow + 128) * Kb + kb + lcol * 8;
            cp16(s0a + OFF_BHI, gB0 + gb0);
            cp16(s1a + OFF_BHI, gB0 + gb1);
            cp16(s0a + OFF_BLO, gB1 + gb0);
            cp16(s1a + OFF_BLO, gB1 + gb1);
        }
        asm volatile("cp.async.commit_group;" ::: "memory");
    };

    issue(0);
    issue(1);
    for (int kc = 0; kc < nC; kc++) {
        if (kc + 2 < nC) {
            issue(kc + 2);
            asm volatile("cp.async.wait_group 2;" ::: "memory");
        } else {
            asm volatile("cp.async.wait_group 0;" ::: "memory");
        }
        __syncthreads();

        const uint32_t so = sb + (kc % NSTAGE) * STAGE_BYTES;
        #pragma unroll
        for (int ks = 0; ks < 2; ks++) {
            uint32_t ah[2][4], al[2][4];
            const uint32_t ab = so + aoff + ks * 32;
            ldsm_x4(ah[0], ab);
            ldsm_x4(ah[1], ab + 16 * PITCH);
            ldsm_x4(al[0], ab + OFF_ALO);
            ldsm_x4(al[1], ab + OFF_ALO + 16 * PITCH);
            const uint32_t bb = so + OFF_BHI + boff + ks * 32;
            #pragma unroll
            for (int p = 0; p < 4; p++) {
                uint32_t bh[4], bl[4];
                ldsm_x4(bh, bb + p * 16 * PITCH);
                ldsm_x4(bl, bb + p * 16 * PITCH + B_BYTES);
                #pragma unroll
                for (int mi = 0; mi < 2; mi++) {
                    mma16816(acc[mi][2 * p],     ah[mi], bh);
                    mma16816(acc[mi][2 * p],     ah[mi], bl);
                    mma16816(acc[mi][2 * p],     al[mi], bh);
                    mma16816(acc[mi][2 * p + 1], ah[mi], bh + 2);
                    mma16816(acc[mi][2 * p + 1], ah[mi], bl + 2);
                    mma16816(acc[mi][2 * p + 1], al[mi], bh + 2);
                }
            }
        }
        __syncthreads();
    }

    // ---------------- epilogue -------------------------------------------
    const int mrow = m0 + wm * 32 + (lane >> 2);
    const int nrow = wn * 64 + 2 * (lane & 3);
    #pragma unroll
    for (int mi = 0; mi < 2; mi++) {
        #pragma unroll
        for (int nj = 0; nj < 8; nj++) {
            #pragma unroll
            for (int ci = 0; ci < 4; ci++) {
                const int m = mrow + mi * 16 + (ci >> 1) * 8;
                const long pix = n0 + nrow + nj * 8 + (ci & 1);
                float v = acc[mi][nj][ci];
                if (mode == 3 || mode == 4) v = fmaxf(v + bias[m], 0.f);
                if (mode == 1 || mode == 3) {
                    split_g(v, outHi, outLo, pix * 512 + m);
                } else if (mode == 4) {       // NCHW scatter (convDU geometry)
                    int img = (int)(pix / 288);
                    int rem = (int)(pix - (long)img * 288);
                    int l = rem / 3, s = rem - l * 3;
                    int nb = img >> 5, ck = img & 31;
                    int h = ck * 3 + s;
                    outF[(((long)nb * 512 + m) * 96 + h) * 96 + l] = v;
                } else if (mode == 5) {       // split + H-shuffle -> LR act
                    int p = (int)pix;
                    int n = p / 2304, rem = p - n * 2304;
                    int h = rem / 48, w = rem - h * 48;
                    int h2 = 2 * h + (m >> 9);
                    int ckW = w / 3, s = w - ckW * 3;
                    long pixLR = (long)(n * 16 + ckW) * 288 + h2 * 3 + s;
                    split_g(v, outHi, outLo, pixLR * 512 + (m & 511));
                } else {                      // mode 6: split + W-shuffle -> DU act
                    int p = (int)pix;
                    int img = p / 288, rem = p - img * 288;
                    int h2 = rem / 3, s = rem - h2 * 3;
                    int n = img >> 4, ckW = img & 15;
                    int w = ckW * 3 + s;
                    int w2 = 2 * w + (m >> 9);
                    int ckH = h2 / 3, sH = h2 - ckH * 3;
                    long pixDU = (long)(n * 32 + ckH) * 288 + w2 * 3 + sH;
                    split_g(v, outHi, outLo, pixDU * 512 + (m & 511));
                }
            }
        }
    }
}

// ------------------------- prep kernels -----------------------------------
__global__ void splitW(const float* __restrict__ src, __half* __restrict__ hi,
                       __half* __restrict__ lo, int count) {
    int i = blockIdx.x * 256 + threadIdx.x;
    if (i < count) split_g(src[i], hi, lo, i);
}

// conv weight reorder + split: dst[co*4608 + t*512 + ci]
__global__ void splitWConv(const float* __restrict__ w, __half* __restrict__ hi,
                           __half* __restrict__ lo, int mulL, int mulS) {
    int i = blockIdx.x * 256 + threadIdx.x;
    int ci = i & 511;
    int t = (i >> 9) % 9;
    int co = i / 4608;
    int dl = t / 3, ds = t % 3;
    float v = w[(long)co * 4608 + ci * 9 + dl * mulL + ds * mulS];
    split_g(v, hi, lo, (long)co * 4608 + t * 512 + ci);
}

// x[n,c,h,w] -> B[pix(n,h,w), c] split
__global__ void gatherX(const float* __restrict__ x, __half* __restrict__ bhi,
                        __half* __restrict__ blo) {
    int i = blockIdx.x * 256 + threadIdx.x;
    int c4 = i & 511;
    int pix = i >> 9;
    int n = pix / 2304;
    int p = pix - n * 2304;
    const float* xs = x + ((long)n * 2048 + c4 * 4) * 2304 + p;
    long o = (long)pix * 2048 + c4 * 4;
    split_g(xs[0],    bhi, blo, o + 0);
    split_g(xs[2304], bhi, blo, o + 1);
    split_g(xs[4608], bhi, blo, o + 2);
    split_g(xs[6912], bhi, blo, o + 3);
}

// ---------------------------------------------------------------------------
// kernel_launch.  Inputs: x, w_channel, w_w, w_H, w_lr, b_lr, w_du, b_du
// ---------------------------------------------------------------------------
extern "C" void kernel_launch(void* const* d_in, const int* in_sizes, int n_in,
                              void* d_out, int out_size) {
    const float* x         = (const float*)d_in[0];
    const float* w_channel = (const float*)d_in[1];
    const float* w_w       = (const float*)d_in[2];
    const float* w_H       = (const float*)d_in[3];
    const float* w_lr      = (const float*)d_in[4];
    const float* b_lr      = (const float*)d_in[5];
    const float* w_du      = (const float*)d_in[6];
    const float* b_du      = (const float*)d_in[7];
    float* out = (float*)d_out;

    __half *aHi, *aLo, *bHi, *bLo, *cHi, *cLo, *B2hi, *B2lo;
    __half *wch_hi, *wch_lo, *ww_hi, *ww_lo, *wH_hi, *wH_lo;
    __half *wlr_hi, *wlr_lo, *wdu_hi, *wdu_lo;
    cudaGetSymbolAddress((void**)&aHi, g_aHi);
    cudaGetSymbolAddress((void**)&aLo, g_aLo);
    cudaGetSymbolAddress((void**)&bHi, g_bHi);
    cudaGetSymbolAddress((void**)&bLo, g_bLo);
    cudaGetSymbolAddress((void**)&cHi, g_cHi);
    cudaGetSymbolAddress((void**)&cLo, g_cLo);
    cudaGetSymbolAddress((void**)&B2hi, g_B2hi);
    cudaGetSymbolAddress((void**)&B2lo, g_B2lo);
    cudaGetSymbolAddress((void**)&wch_hi, g_wch_hi);
    cudaGetSymbolAddress((void**)&wch_lo, g_wch_lo);
    cudaGetSymbolAddress((void**)&ww_hi, g_ww_hi);
    cudaGetSymbolAddress((void**)&ww_lo, g_ww_lo);
    cudaGetSymbolAddress((void**)&wH_hi, g_wH_hi);
    cudaGetSymbolAddress((void**)&wH_lo, g_wH_lo);
    cudaGetSymbolAddress((void**)&wlr_hi, g_wlr_hi);
    cudaGetSymbolAddress((void**)&wlr_lo, g_wlr_lo);
    cudaGetSymbolAddress((void**)&wdu_hi, g_wdu_hi);
    cudaGetSymbolAddress((void**)&wdu_lo, g_wdu_lo);

    cudaFuncSetAttribute(gemm_hmma, cudaFuncAttributeMaxDynamicSharedMemorySize,
                         SMEM_TOTAL);

    // weight prep
    splitW<<<(512 * 2048) / 256, 256>>>(w_channel, wch_hi, wch_lo, 512 * 2048);
    splitW<<<(1024 * 512) / 256, 256>>>(w_w, ww_hi, ww_lo, 1024 * 512);
    splitW<<<(1024 * 512) / 256, 256>>>(w_H, wH_hi, wH_lo, 1024 * 512);
    splitWConv<<<(512 * 4608) / 256, 256>>>(w_lr, wlr_hi, wlr_lo, 3, 1);
    splitWConv<<<(512 * 4608) / 256, 256>>>(w_du, wdu_hi, wdu_lo, 1, 3);

    // stage 1: split(x) -> a [9216,2048]; y1 = w_channel @ x -> split B2
    gatherX<<<(9216 * 512) / 256, 256>>>(x, aHi, aLo);
    gemm_hmma<<<dim3(4, 36), 512, SMEM_TOTAL>>>(
        wch_hi, wch_lo, aHi, aLo, 2048, 2048, 0, 1, nullptr,
        nullptr, B2hi, B2lo);

    // stage 2: w_w @ y1, epilogue = H-shuffle + split -> LR act b [18432,512]
    gemm_hmma<<<dim3(8, 36), 512, SMEM_TOTAL>>>(
        ww_hi, ww_lo, B2hi, B2lo, 512, 512, 0, 5, nullptr,
        nullptr, bHi, bLo);

    // convLR pass 1 -> split c [18432,512]
    gemm_hmma<<<dim3(4, 72), 512, SMEM_TOTAL>>>(
        wlr_hi, wlr_lo, bHi, bLo, 4608, 512, 1, 3, b_lr,
        nullptr, cHi, cLo);

    // convLR pass 2 -> split a [18432,512]
    gemm_hmma<<<dim3(4, 72), 512, SMEM_TOTAL>>>(
        wlr_hi, wlr_lo, cHi, cLo, 4608, 512, 1, 3, b_lr,
        nullptr, aHi, aLo);

    // w_H stage: epilogue = W-shuffle + split -> DU act b [36864,512]
    gemm_hmma<<<dim3(8, 72), 512, SMEM_TOTAL>>>(
        wH_hi, wH_lo, aHi, aLo, 512, 512, 0, 6, nullptr,
        nullptr, bHi, bLo);

    // convDU pass 1 -> split a [36864,512]
    gemm_hmma<<<dim3(4, 144), 512, SMEM_TOTAL>>>(
        wdu_hi, wdu_lo, bHi, bLo, 4608, 512, 1, 3, b_du,
        nullptr, aHi, aLo);

    // convDU pass 2 -> final NCHW output
    gemm_hmma<<<dim3(4, 144), 512, SMEM_TOTAL>>>(
        wdu_hi, wdu_lo, aHi, aLo, 4608, 512, 1, 4, b_du,
        out, nullptr, nullptr);
}

// round 10
// speedup vs baseline: 1.1793x; 1.1793x over previous
#include <cuda_runtime.h>
#include <cuda_fp16.h>
#include <cstdint>

// ===========================================================================
// SSRupsampling via HMMA (mma.sync m16n8k16, fp32 accum), fp16 3-product
// split. Conv B = shifted view of compact [pix,512] act (no im2col).
// GEMM: 128x128 block tile, 32x64 warp tile, 256 thr, 2 CTA/SM.
// NEW: 128B-XOR-swizzled smem tiles (8KB/tile), 3-stage cp.async pipeline,
// single __syncthreads per K-chunk. Pixel shuffles fused into epilogues.
// ===========================================================================

// ------------------------------ scratch -----------------------------------
__device__ __half g_aHi[36864L * 512], g_aLo[36864L * 512];
__device__ __half g_bHi[36864L * 512], g_bLo[36864L * 512];
__device__ __half g_cHi[18432 * 512],  g_cLo[18432 * 512];
__device__ __half g_B2hi[9216 * 512],  g_B2lo[9216 * 512];
__device__ __half g_wch_hi[512 * 2048], g_wch_lo[512 * 2048];
__device__ __half g_ww_hi[1024 * 512],  g_ww_lo[1024 * 512];
__device__ __half g_wH_hi[1024 * 512],  g_wH_lo[1024 * 512];
__device__ __half g_wlr_hi[512 * 4608], g_wlr_lo[512 * 4608];
__device__ __half g_wdu_hi[512 * 4608], g_wdu_lo[512 * 4608];

// ------------------------------ helpers -----------------------------------
__device__ __forceinline__ uint32_t smem_u32(const void* p) {
    uint32_t a;
    asm("{ .reg .u64 t; cvta.to.shared.u64 t, %1; cvt.u32.u64 %0, t; }"
        : "=r"(a) : "l"(p));
    return a;
}
__device__ __forceinline__ void ldsm_x4(uint32_t* r, uint32_t addr) {
    asm volatile("ldmatrix.sync.aligned.m8n8.x4.shared.b16 {%0,%1,%2,%3}, [%4];"
                 : "=r"(r[0]), "=r"(r[1]), "=r"(r[2]), "=r"(r[3]) : "r"(addr));
}
__device__ __forceinline__ void mma16816(float* c, const uint32_t* a,
                                         const uint32_t* b) {
    asm volatile(
        "mma.sync.aligned.m16n8k16.row.col.f32.f16.f16.f32 "
        "{%0,%1,%2,%3}, {%4,%5,%6,%7}, {%8,%9}, {%0,%1,%2,%3};"
        : "+f"(c[0]), "+f"(c[1]), "+f"(c[2]), "+f"(c[3])
        : "r"(a[0]), "r"(a[1]), "r"(a[2]), "r"(a[3]), "r"(b[0]), "r"(b[1]));
}
__device__ __forceinline__ void cp16(uint32_t sa, const void* ga) {
    asm volatile("cp.async.cg.shared.global [%0], [%1], 16;"
                 :: "r"(sa), "l"(ga));
}
__device__ __forceinline__ void cp16p(uint32_t sa, const void* ga, int sz) {
    asm volatile("cp.async.cg.shared.global [%0], [%1], 16, %2;"
                 :: "r"(sa), "l"(ga), "r"(sz));
}

#define BK 32
#define TILE_BYTES 8192            // 128 rows x 64B, swizzled
#define OFF_AHI 0
#define OFF_ALO TILE_BYTES
#define OFF_BHI (2 * TILE_BYTES)
#define OFF_BLO (3 * TILE_BYTES)
#define STAGE_BYTES (4 * TILE_BYTES)   // 32768
#define NSTAGE 3
#define SMEM_TOTAL (NSTAGE * STAGE_BYTES)   // 98304 per CTA

// swizzled byte offset of the 16B unit (row, lcol), row 0..127, lcol 0..3
__device__ __forceinline__ uint32_t swz(int row, int lcol) {
    return (uint32_t)((row >> 1) * 128 +
                      ((((row & 1) * 4 + lcol) ^ ((row >> 1) & 7)) * 16));
}

__device__ __forceinline__ void split_g(float v, __half* hi, __half* lo,
                                        long idx) {
    __half h = __float2half_rn(v);
    hi[idx] = h;
    lo[idx] = __float2half_rn(v - __half2float(h));
}

// ---------------------------------------------------------------------------
// GEMM: D[m,n] = sum_k A[m,k]*B[n,k], fp16 x3 split, fp32 accum.
// Block tile 128x128, BK=32, 256 threads (8 warps, 4m x 2n), warp tile 32x64.
// conv!=0: K=4608 logical (9 taps x 512); B read from [Npix,512] with row
// shift (t-4) and l/s boundary mask (pix = img*288 + l*3 + s).
// Modes: 1 split [pix,512]; 3 bias+relu split [pix,512];
//        4 bias+relu NCHW scatter (final); 5 split + H-shuffle (stage2);
//        6 split + W-shuffle (w_H stage).
// ---------------------------------------------------------------------------
__global__ __launch_bounds__(256, 2)
void gemm_hmma(const __half* __restrict__ Ahi, const __half* __restrict__ Alo,
               const __half* __restrict__ Bhi, const __half* __restrict__ Blo,
               int K, int Kb, int conv, int mode,
               const float* __restrict__ bias, float* __restrict__ outF,
               __half* __restrict__ outHi, __half* __restrict__ outLo) {
    extern __shared__ char smem[];
    const uint32_t sb = smem_u32(smem);
    const int tid = threadIdx.x;
    const int lane = tid & 31, wid = tid >> 5;
    const int wm = wid >> 1, wn = wid & 1;
    const int m0 = blockIdx.x * 128;
    const long n0 = (long)blockIdx.y * 128;

    const __half* gA0 = Ahi + (long)m0 * K;
    const __half* gA1 = Alo + (long)m0 * K;
    const __half* gB0 = Bhi + n0 * Kb;
    const __half* gB1 = Blo + n0 * Kb;

    const int lrow0 = tid >> 2, lcol = tid & 3;
    const int lrow1 = lrow0 + 64;
    const uint32_t sw0 = swz(lrow0, lcol);
    const uint32_t sw1 = swz(lrow1, lcol);

    // conv B-row geometry (pix = img*288 + l*3 + s)
    int l0 = 0, s0 = 0, l1 = 0, s1 = 0;
    if (conv) {
        const int p0 = (int)n0 + lrow0, p1 = (int)n0 + lrow1;
        s0 = p0 % 3; l0 = (p0 / 3) % 96;
        s1 = p1 % 3; l1 = (p1 / 3) % 96;
    }

    // ldmatrix swizzled bases (ks=0); addr(ks=1) = addr ^ 32; +16 rows = +1024
    const int lg = lane >> 3, lr = lane & 7;
    const uint32_t abase = swz(wm * 32 + (lg & 1) * 8 + lr, lg >> 1);
    const uint32_t bbase = swz(wn * 64 + (lg >> 1) * 8 + lr, lg & 1);

    float acc[2][8][4];
    #pragma unroll
    for (int i = 0; i < 2; i++)
        #pragma unroll
        for (int j = 0; j < 8; j++)
            #pragma unroll
            for (int c = 0; c < 4; c++) acc[i][j][c] = 0.f;

    const int nC = K / BK;

    auto issue = [&](int kc) {
        const uint32_t so = sb + (kc % NSTAGE) * STAGE_BYTES;
        // A: linear in k
        {
            const long kb = (long)kc * BK;
            const long ga0 = (long)lrow0 * K + kb + lcol * 8;
            const long ga1 = (long)lrow1 * K + kb + lcol * 8;
            cp16(so + OFF_AHI + sw0, gA0 + ga0);
            cp16(so + OFF_AHI + sw1, gA0 + ga1);
            cp16(so + OFF_ALO + sw0, gA1 + ga0);
            cp16(so + OFF_ALO + sw1, gA1 + ga1);
        }
        // B: shifted view for conv, linear otherwise
        if (conv) {
            const int t = kc >> 4;                // tap 0..8
            const int dlm = t / 3 - 1, dsm = t % 3 - 1;
            const int koff = (kc & 15) * 32 + lcol * 8;
            const long rs = (long)(t - 4) * Kb;
            const int v0 = ((unsigned)(l0 + dlm) < 96u &&
                            (unsigned)(s0 + dsm) < 3u) ? 16 : 0;
            const int v1 = ((unsigned)(l1 + dlm) < 96u &&
                            (unsigned)(s1 + dsm) < 3u) ? 16 : 0;
            const long gb0 = (long)lrow0 * Kb + rs + koff;
            const long gb1 = (long)lrow1 * Kb + rs + koff;
            cp16p(so + OFF_BHI + sw0, gB0 + gb0, v0);
            cp16p(so + OFF_BHI + sw1, gB0 + gb1, v1);
            cp16p(so + OFF_BLO + sw0, gB1 + gb0, v0);
            cp16p(so + OFF_BLO + sw1, gB1 + gb1, v1);
        } else {
            const long kb = (long)kc * BK;
            const long gb0 = (long)lrow0 * Kb + kb + lcol * 8;
            const long gb1 = (long)lrow1 * Kb + kb + lcol * 8;
            cp16(so + OFF_BHI + sw0, gB0 + gb0);
            cp16(so + OFF_BHI + sw1, gB0 + gb1);
            cp16(so + OFF_BLO + sw0, gB1 + gb0);
            cp16(so + OFF_BLO + sw1, gB1 + gb1);
        }
        asm volatile("cp.async.commit_group;" ::: "memory");
    };

    issue(0);
    issue(1);
    for (int kc = 0; kc < nC; kc++) {
        if (kc + 1 < nC) {
            asm volatile("cp.async.wait_group 1;" ::: "memory");
        } else {
            asm volatile("cp.async.wait_group 0;" ::: "memory");
        }
        __syncthreads();              // kc data visible; kc-1 reads done
        if (kc + 2 < nC) issue(kc + 2);   // overwrites buffer of chunk kc-1

        const uint32_t so = sb + (kc % NSTAGE) * STAGE_BYTES;
        #pragma unroll
        for (int ks = 0; ks < 2; ks++) {
            const uint32_t axor = ks * 32;
            uint32_t ah[2][4], al[2][4];
            const uint32_t ab = so + OFF_AHI + abase;
            ldsm_x4(ah[0], (ab) ^ axor);
            ldsm_x4(ah[1], (ab + 1024) ^ axor);
            ldsm_x4(al[0], (ab + TILE_BYTES) ^ axor);
            ldsm_x4(al[1], (ab + TILE_BYTES + 1024) ^ axor);
            const uint32_t bb = so + OFF_BHI + bbase;
            #pragma unroll
            for (int p = 0; p < 4; p++) {
                uint32_t bh[4], bl[4];
                ldsm_x4(bh, (bb + p * 1024) ^ axor);
                ldsm_x4(bl, (bb + p * 1024 + TILE_BYTES) ^ axor);
                #pragma unroll
                for (int mi = 0; mi < 2; mi++) {
                    mma16816(acc[mi][2 * p],     ah[mi], bh);
                    mma16816(acc[mi][2 * p],     ah[mi], bl);
                    mma16816(acc[mi][2 * p],     al[mi], bh);
                    mma16816(acc[mi][2 * p + 1], ah[mi], bh + 2);
                    mma16816(acc[mi][2 * p + 1], ah[mi], bl + 2);
                    mma16816(acc[mi][2 * p + 1], al[mi], bh + 2);
                }
            }
        }
    }

    // ---------------- epilogue -------------------------------------------
    const int mrow = m0 + wm * 32 + (lane >> 2);
    const int nrow = wn * 64 + 2 * (lane & 3);
    #pragma unroll
    for (int mi = 0; mi < 2; mi++) {
        #pragma unroll
        for (int nj = 0; nj < 8; nj++) {
            #pragma unroll
            for (int ci = 0; ci < 4; ci++) {
                const int m = mrow + mi * 16 + (ci >> 1) * 8;
                const long pix = n0 + nrow + nj * 8 + (ci & 1);
                float v = acc[mi][nj][ci];
                if (mode == 3 || mode == 4) v = fmaxf(v + bias[m], 0.f);
                if (mode == 1 || mode == 3) {
                    split_g(v, outHi, outLo, pix * 512 + m);
                } else if (mode == 4) {       // NCHW scatter (convDU geometry)
                    int img = (int)(pix / 288);
                    int rem = (int)(pix - (long)img * 288);
                    int l = rem / 3, s = rem - l * 3;
                    int nb = img >> 5, ck = img & 31;
                    int h = ck * 3 + s;
                    outF[(((long)nb * 512 + m) * 96 + h) * 96 + l] = v;
                } else if (mode == 5) {       // split + H-shuffle -> LR act
                    int p = (int)pix;
                    int n = p / 2304, rem = p - n * 2304;
                    int h = rem / 48, w = rem - h * 48;
                    int h2 = 2 * h + (m >> 9);
                    int ckW = w / 3, s = w - ckW * 3;
                    long pixLR = (long)(n * 16 + ckW) * 288 + h2 * 3 + s;
                    split_g(v, outHi, outLo, pixLR * 512 + (m & 511));
                } else {                      // mode 6: split + W-shuffle -> DU act
                    int p = (int)pix;
                    int img = p / 288, rem = p - img * 288;
                    int h2 = rem / 3, s = rem - h2 * 3;
                    int n = img >> 4, ckW = img & 15;
                    int w = ckW * 3 + s;
                    int w2 = 2 * w + (m >> 9);
                    int ckH = h2 / 3, sH = h2 - ckH * 3;
                    long pixDU = (long)(n * 32 + ckH) * 288 + w2 * 3 + sH;
                    split_g(v, outHi, outLo, pixDU * 512 + (m & 511));
                }
            }
        }
    }
}

// ------------------------- prep kernels -----------------------------------
__global__ void splitW(const float* __restrict__ src, __half* __restrict__ hi,
                       __half* __restrict__ lo, int count) {
    int i = blockIdx.x * 256 + threadIdx.x;
    if (i < count) split_g(src[i], hi, lo, i);
}

// conv weight reorder + split: dst[co*4608 + t*512 + ci]
__global__ void splitWConv(const float* __restrict__ w, __half* __restrict__ hi,
                           __half* __restrict__ lo, int mulL, int mulS) {
    int i = blockIdx.x * 256 + threadIdx.x;
    int ci = i & 511;
    int t = (i >> 9) % 9;
    int co = i / 4608;
    int dl = t / 3, ds = t % 3;
    float v = w[(long)co * 4608 + ci * 9 + dl * mulL + ds * mulS];
    split_g(v, hi, lo, (long)co * 4608 + t * 512 + ci);
}

// x[n,c,h,w] -> B[pix(n,h,w), c] split
__global__ void gatherX(const float* __restrict__ x, __half* __restrict__ bhi,
                        __half* __restrict__ blo) {
    int i = blockIdx.x * 256 + threadIdx.x;
    int c4 = i & 511;
    int pix = i >> 9;
    int n = pix / 2304;
    int p = pix - n * 2304;
    const float* xs = x + ((long)n * 2048 + c4 * 4) * 2304 + p;
    long o = (long)pix * 2048 + c4 * 4;
    split_g(xs[0],    bhi, blo, o + 0);
    split_g(xs[2304], bhi, blo, o + 1);
    split_g(xs[4608], bhi, blo, o + 2);
    split_g(xs[6912], bhi, blo, o + 3);
}

// ---------------------------------------------------------------------------
// kernel_launch.  Inputs: x, w_channel, w_w, w_H, w_lr, b_lr, w_du, b_du
// ---------------------------------------------------------------------------
extern "C" void kernel_launch(void* const* d_in, const int* in_sizes, int n_in,
                              void* d_out, int out_size) {
    const float* x         = (const float*)d_in[0];
    const float* w_channel = (const float*)d_in[1];
    const float* w_w       = (const float*)d_in[2];
    const float* w_H       = (const float*)d_in[3];
    const float* w_lr      = (const float*)d_in[4];
    const float* b_lr      = (const float*)d_in[5];
    const float* w_du      = (const float*)d_in[6];
    const float* b_du      = (const float*)d_in[7];
    float* out = (float*)d_out;

    __half *aHi, *aLo, *bHi, *bLo, *cHi, *cLo, *B2hi, *B2lo;
    __half *wch_hi, *wch_lo, *ww_hi, *ww_lo, *wH_hi, *wH_lo;
    __half *wlr_hi, *wlr_lo, *wdu_hi, *wdu_lo;
    cudaGetSymbolAddress((void**)&aHi, g_aHi);
    cudaGetSymbolAddress((void**)&aLo, g_aLo);
    cudaGetSymbolAddress((void**)&bHi, g_bHi);
    cudaGetSymbolAddress((void**)&bLo, g_bLo);
    cudaGetSymbolAddress((void**)&cHi, g_cHi);
    cudaGetSymbolAddress((void**)&cLo, g_cLo);
    cudaGetSymbolAddress((void**)&B2hi, g_B2hi);
    cudaGetSymbolAddress((void**)&B2lo, g_B2lo);
    cudaGetSymbolAddress((void**)&wch_hi, g_wch_hi);
    cudaGetSymbolAddress((void**)&wch_lo, g_wch_lo);
    cudaGetSymbolAddress((void**)&ww_hi, g_ww_hi);
    cudaGetSymbolAddress((void**)&ww_lo, g_ww_lo);
    cudaGetSymbolAddress((void**)&wH_hi, g_wH_hi);
    cudaGetSymbolAddress((void**)&wH_lo, g_wH_lo);
    cudaGetSymbolAddress((void**)&wlr_hi, g_wlr_hi);
    cudaGetSymbolAddress((void**)&wlr_lo, g_wlr_lo);
    cudaGetSymbolAddress((void**)&wdu_hi, g_wdu_hi);
    cudaGetSymbolAddress((void**)&wdu_lo, g_wdu_lo);

    cudaFuncSetAttribute(gemm_hmma, cudaFuncAttributeMaxDynamicSharedMemorySize,
                         SMEM_TOTAL);

    // weight prep
    splitW<<<(512 * 2048) / 256, 256>>>(w_channel, wch_hi, wch_lo, 512 * 2048);
    splitW<<<(1024 * 512) / 256, 256>>>(w_w, ww_hi, ww_lo, 1024 * 512);
    splitW<<<(1024 * 512) / 256, 256>>>(w_H, wH_hi, wH_lo, 1024 * 512);
    splitWConv<<<(512 * 4608) / 256, 256>>>(w_lr, wlr_hi, wlr_lo, 3, 1);
    splitWConv<<<(512 * 4608) / 256, 256>>>(w_du, wdu_hi, wdu_lo, 1, 3);

    // stage 1: split(x) -> a [9216,2048]; y1 = w_channel @ x -> split B2
    gatherX<<<(9216 * 512) / 256, 256>>>(x, aHi, aLo);
    gemm_hmma<<<dim3(4, 72), 256, SMEM_TOTAL>>>(
        wch_hi, wch_lo, aHi, aLo, 2048, 2048, 0, 1, nullptr,
        nullptr, B2hi, B2lo);

    // stage 2: w_w @ y1, epilogue = H-shuffle + split -> LR act b [18432,512]
    gemm_hmma<<<dim3(8, 72), 256, SMEM_TOTAL>>>(
        ww_hi, ww_lo, B2hi, B2lo, 512, 512, 0, 5, nullptr,
        nullptr, bHi, bLo);

    // convLR pass 1 -> split c [18432,512]
    gemm_hmma<<<dim3(4, 144), 256, SMEM_TOTAL>>>(
        wlr_hi, wlr_lo, bHi, bLo, 4608, 512, 1, 3, b_lr,
        nullptr, cHi, cLo);

    // convLR pass 2 -> split a [18432,512]
    gemm_hmma<<<dim3(4, 144), 256, SMEM_TOTAL>>>(
        wlr_hi, wlr_lo, cHi, cLo, 4608, 512, 1, 3, b_lr,
        nullptr, aHi, aLo);

    // w_H stage: epilogue = W-shuffle + split -> DU act b [36864,512]
    gemm_hmma<<<dim3(8, 144), 256, SMEM_TOTAL>>>(
        wH_hi, wH_lo, aHi, aLo, 512, 512, 0, 6, nullptr,
        nullptr, bHi, bLo);

    // convDU pass 1 -> split a [36864,512]
    gemm_hmma<<<dim3(4, 288), 256, SMEM_TOTAL>>>(
        wdu_hi, wdu_lo, bHi, bLo, 4608, 512, 1, 3, b_du,
        nullptr, aHi, aLo);

    // convDU pass 2 -> final NCHW output
    gemm_hmma<<<dim3(4, 288), 256, SMEM_TOTAL>>>(
        wdu_hi, wdu_lo, aHi, aLo, 4608, 512, 1, 4, b_du,
        out, nullptr, nullptr);
}

// round 11
// speedup vs baseline: 1.3929x; 1.1812x over previous
#include <cuda_runtime.h>
#include <cuda_fp16.h>
#include <cstdint>

// ===========================================================================
// SSRupsampling via HMMA (mma.sync m16n8k16, fp32 accum), fp16 3-product
// split. Conv B = shifted view of S-MAJOR [pix,512] act: r = s*S + img*96 + l.
// Uniform s per 128-row N-tile -> invalid-ds taps skipped entirely (22% of
// conv MMA work removed). 128x128 block tile, 32x64 warp tile, 256 thr,
// 2 CTA/SM, swizzled smem, 3-stage cp.async, single sync per chunk.
// ===========================================================================

// ------------------------------ scratch -----------------------------------
__device__ __half g_aHi[36864L * 512], g_aLo[36864L * 512];
__device__ __half g_bHi[36864L * 512], g_bLo[36864L * 512];
__device__ __half g_cHi[18432 * 512],  g_cLo[18432 * 512];
__device__ __half g_B2hi[9216 * 512],  g_B2lo[9216 * 512];
__device__ __half g_wch_hi[512 * 2048], g_wch_lo[512 * 2048];
__device__ __half g_ww_hi[1024 * 512],  g_ww_lo[1024 * 512];
__device__ __half g_wH_hi[1024 * 512],  g_wH_lo[1024 * 512];
__device__ __half g_wlr_hi[512 * 4608], g_wlr_lo[512 * 4608];
__device__ __half g_wdu_hi[512 * 4608], g_wdu_lo[512 * 4608];

// ------------------------------ helpers -----------------------------------
__device__ __forceinline__ uint32_t smem_u32(const void* p) {
    uint32_t a;
    asm("{ .reg .u64 t; cvta.to.shared.u64 t, %1; cvt.u32.u64 %0, t; }"
        : "=r"(a) : "l"(p));
    return a;
}
__device__ __forceinline__ void ldsm_x4(uint32_t* r, uint32_t addr) {
    asm volatile("ldmatrix.sync.aligned.m8n8.x4.shared.b16 {%0,%1,%2,%3}, [%4];"
                 : "=r"(r[0]), "=r"(r[1]), "=r"(r[2]), "=r"(r[3]) : "r"(addr));
}
__device__ __forceinline__ void mma16816(float* c, const uint32_t* a,
                                         const uint32_t* b) {
    asm volatile(
        "mma.sync.aligned.m16n8k16.row.col.f32.f16.f16.f32 "
        "{%0,%1,%2,%3}, {%4,%5,%6,%7}, {%8,%9}, {%0,%1,%2,%3};"
        : "+f"(c[0]), "+f"(c[1]), "+f"(c[2]), "+f"(c[3])
        : "r"(a[0]), "r"(a[1]), "r"(a[2]), "r"(a[3]), "r"(b[0]), "r"(b[1]));
}
__device__ __forceinline__ void cp16(uint32_t sa, const void* ga) {
    asm volatile("cp.async.cg.shared.global [%0], [%1], 16;"
                 :: "r"(sa), "l"(ga));
}
__device__ __forceinline__ void cp16p(uint32_t sa, const void* ga, int sz) {
    asm volatile("cp.async.cg.shared.global [%0], [%1], 16, %2;"
                 :: "r"(sa), "l"(ga), "r"(sz));
}

#define BK 32
#define TILE_BYTES 8192            // 128 rows x 64B, swizzled
#define OFF_AHI 0
#define OFF_ALO TILE_BYTES
#define OFF_BHI (2 * TILE_BYTES)
#define OFF_BLO (3 * TILE_BYTES)
#define STAGE_BYTES (4 * TILE_BYTES)   // 32768
#define NSTAGE 3
#define SMEM_TOTAL (NSTAGE * STAGE_BYTES)   // 98304 per CTA

// swizzled byte offset of the 16B unit (row, lcol), row 0..127, lcol 0..3
__device__ __forceinline__ uint32_t swz(int row, int lcol) {
    return (uint32_t)((row >> 1) * 128 +
                      ((((row & 1) * 4 + lcol) ^ ((row >> 1) & 7)) * 16));
}

__device__ __forceinline__ void split_g(float v, __half* hi, __half* lo,
                                        long idx) {
    __half h = __float2half_rn(v);
    hi[idx] = h;
    lo[idx] = __float2half_rn(v - __half2float(h));
}

// ---------------------------------------------------------------------------
// GEMM: D[m,n] = sum_k A[m,k]*B[n,k], fp16 x3 split, fp32 accum.
// Block tile 128x128, BK=32, 256 threads (8 warps, 4m x 2n), warp tile 32x64.
// conv!=0: B read from S-MAJOR [Npix,512] act, r = s*S + img*96 + l.
//   N-tile has uniform s; K-loop covers only valid taps:
//   dl in {0,1,2} always (l-masked per row); ds in valid range for s.
// Modes: 1 split [pix,512]; 3 bias+relu split [pix,512];
//        4 bias+relu NCHW scatter (DU s-major rows); 5 split + H-shuffle
//        (stage2 -> LR s-major); 6 split + W-shuffle (w_H -> DU s-major).
// ---------------------------------------------------------------------------
__global__ __launch_bounds__(256, 2)
void gemm_hmma(const __half* __restrict__ Ahi, const __half* __restrict__ Alo,
               const __half* __restrict__ Bhi, const __half* __restrict__ Blo,
               int K, int Kb, int conv, int S, int mode,
               const float* __restrict__ bias, float* __restrict__ outF,
               __half* __restrict__ outHi, __half* __restrict__ outLo) {
    extern __shared__ char smem[];
    const uint32_t sb = smem_u32(smem);
    const int tid = threadIdx.x;
    const int lane = tid & 31, wid = tid >> 5;
    const int wm = wid >> 1, wn = wid & 1;
    const int m0 = blockIdx.x * 128;
    const long n0 = (long)blockIdx.y * 128;

    const __half* gA0 = Ahi + (long)m0 * K;
    const __half* gA1 = Alo + (long)m0 * K;
    const __half* gB0 = Bhi + n0 * Kb;
    const __half* gB1 = Blo + n0 * Kb;

    const int lrow0 = tid >> 2, lcol = tid & 3;
    const int lrow1 = lrow0 + 64;
    const uint32_t sw0 = swz(lrow0, lcol);
    const uint32_t sw1 = swz(lrow1, lcol);

    // conv geometry: s uniform per tile; l = r % 96 (S and 96 divide blocks)
    int l0 = 0, l1 = 0, nds = 3, dsmin = -1;
    if (conv) {
        const int sTile = (int)(n0 / S);
        l0 = (int)((n0 + lrow0) % 96);
        l1 = (int)((n0 + lrow1) % 96);
        nds = (sTile == 1) ? 3 : 2;
        dsmin = (sTile == 0) ? 0 : -1;
    }

    // ldmatrix swizzled bases (ks=0); addr(ks=1) = addr ^ 32; +16 rows = +1024
    const int lg = lane >> 3, lr = lane & 7;
    const uint32_t abase = swz(wm * 32 + (lg & 1) * 8 + lr, lg >> 1);
    const uint32_t bbase = swz(wn * 64 + (lg >> 1) * 8 + lr, lg & 1);

    float acc[2][8][4];
    #pragma unroll
    for (int i = 0; i < 2; i++)
        #pragma unroll
        for (int j = 0; j < 8; j++)
            #pragma unroll
            for (int c = 0; c < 4; c++) acc[i][j][c] = 0.f;

    const int nC = conv ? (3 * nds * 16) : (K / BK);

    auto issue = [&](int kc) {
        const uint32_t so = sb + (kc % NSTAGE) * STAGE_BYTES;
        if (conv) {
            const int ti = kc >> 4;
            const int dlm = ti / nds - 1;             // -1, 0, +1
            const int dsm = dsmin + ti % nds;         // valid ds only
            const int t = (dlm + 1) * 3 + (dsm + 1);  // weight tap index
            const int koff = (kc & 15) * 32 + lcol * 8;
            // A: weight k = t*512 + koff
            const long ga0 = (long)lrow0 * K + t * 512 + koff;
            const long ga1 = (long)lrow1 * K + t * 512 + koff;
            cp16(so + OFF_AHI + sw0, gA0 + ga0);
            cp16(so + OFF_AHI + sw1, gA0 + ga1);
            cp16(so + OFF_ALO + sw0, gA1 + ga0);
            cp16(so + OFF_ALO + sw1, gA1 + ga1);
            // B: shifted rows, l-mask only (s-mask handled by tap skip)
            const long rs = (long)(dlm + dsm * S) * Kb;
            const int v0 = ((unsigned)(l0 + dlm) < 96u) ? 16 : 0;
            const int v1 = ((unsigned)(l1 + dlm) < 96u) ? 16 : 0;
            const long gb0 = (long)lrow0 * Kb + rs + koff;
            const long gb1 = (long)lrow1 * Kb + rs + koff;
            cp16p(so + OFF_BHI + sw0, gB0 + gb0, v0);
            cp16p(so + OFF_BHI + sw1, gB0 + gb1, v1);
            cp16p(so + OFF_BLO + sw0, gB1 + gb0, v0);
            cp16p(so + OFF_BLO + sw1, gB1 + gb1, v1);
        } else {
            const long kb = (long)kc * BK;
            const long ga0 = (long)lrow0 * K + kb + lcol * 8;
            const long ga1 = (long)lrow1 * K + kb + lcol * 8;
            cp16(so + OFF_AHI + sw0, gA0 + ga0);
            cp16(so + OFF_AHI + sw1, gA0 + ga1);
            cp16(so + OFF_ALO + sw0, gA1 + ga0);
            cp16(so + OFF_ALO + sw1, gA1 + ga1);
            const long gb0 = (long)lrow0 * Kb + kb + lcol * 8;
            const long gb1 = (long)lrow1 * Kb + kb + lcol * 8;
            cp16(so + OFF_BHI + sw0, gB0 + gb0);
            cp16(so + OFF_BHI + sw1, gB0 + gb1);
            cp16(so + OFF_BLO + sw0, gB1 + gb0);
            cp16(so + OFF_BLO + sw1, gB1 + gb1);
        }
        asm volatile("cp.async.commit_group;" ::: "memory");
    };

    issue(0);
    issue(1);
    for (int kc = 0; kc < nC; kc++) {
        if (kc + 1 < nC) {
            asm volatile("cp.async.wait_group 1;" ::: "memory");
        } else {
            asm volatile("cp.async.wait_group 0;" ::: "memory");
        }
        __syncthreads();              // kc data visible; kc-1 reads done
        if (kc + 2 < nC) issue(kc + 2);   // overwrites buffer of chunk kc-1

        const uint32_t so = sb + (kc % NSTAGE) * STAGE_BYTES;
        #pragma unroll
        for (int ks = 0; ks < 2; ks++) {
            const uint32_t axor = ks * 32;
            uint32_t ah[2][4], al[2][4];
            const uint32_t ab = so + OFF_AHI + abase;
            ldsm_x4(ah[0], (ab) ^ axor);
            ldsm_x4(ah[1], (ab + 1024) ^ axor);
            ldsm_x4(al[0], (ab + TILE_BYTES) ^ axor);
            ldsm_x4(al[1], (ab + TILE_BYTES + 1024) ^ axor);
            const uint32_t bb = so + OFF_BHI + bbase;
            #pragma unroll
            for (int p = 0; p < 4; p++) {
                uint32_t bh[4], bl[4];
                ldsm_x4(bh, (bb + p * 1024) ^ axor);
                ldsm_x4(bl, (bb + p * 1024 + TILE_BYTES) ^ axor);
                #pragma unroll
                for (int mi = 0; mi < 2; mi++) {
                    mma16816(acc[mi][2 * p],     ah[mi], bh);
                    mma16816(acc[mi][2 * p],     ah[mi], bl);
                    mma16816(acc[mi][2 * p],     al[mi], bh);
                    mma16816(acc[mi][2 * p + 1], ah[mi], bh + 2);
                    mma16816(acc[mi][2 * p + 1], ah[mi], bl + 2);
                    mma16816(acc[mi][2 * p + 1], al[mi], bh + 2);
                }
            }
        }
    }

    // ---------------- epilogue -------------------------------------------
    const int mrow = m0 + wm * 32 + (lane >> 2);
    const int nrow = wn * 64 + 2 * (lane & 3);
    #pragma unroll
    for (int mi = 0; mi < 2; mi++) {
        #pragma unroll
        for (int nj = 0; nj < 8; nj++) {
            #pragma unroll
            for (int ci = 0; ci < 4; ci++) {
                const int m = mrow + mi * 16 + (ci >> 1) * 8;
                const long pix = n0 + nrow + nj * 8 + (ci & 1);
                float v = acc[mi][nj][ci];
                if (mode == 3 || mode == 4) v = fmaxf(v + bias[m], 0.f);
                if (mode == 1 || mode == 3) {
                    split_g(v, outHi, outLo, pix * 512 + m);
                } else if (mode == 4) {
                    // final NCHW scatter from DU s-major rows
                    int p = (int)pix;
                    int sD = p / 12288, rem = p % 12288;
                    int img = rem / 96, w2 = rem % 96;
                    int n = img >> 5, ckH = img & 31;
                    int h = ckH * 3 + sD;
                    outF[(((long)n * 512 + m) * 96 + h) * 96 + w2] = v;
                } else if (mode == 5) {
                    // stage2: H-shuffle -> LR act (s-major)
                    int p = (int)pix;
                    int n = p / 2304, rem = p - n * 2304;
                    int h = rem / 48, w = rem - h * 48;
                    int h2 = 2 * h + (m >> 9);
                    int ckW = w / 3, s = w - ckW * 3;
                    long r = (long)s * 6144 + (n * 16 + ckW) * 96 + h2;
                    split_g(v, outHi, outLo, r * 512 + (m & 511));
                } else {
                    // mode 6: w_H out (N = LR s-major rows) -> DU act (s-major)
                    int p = (int)pix;
                    int sL = p / 6144, rem = p % 6144;
                    int img = rem / 96, h2 = rem % 96;
                    int n = img >> 4, ckW = img & 15;
                    int w = ckW * 3 + sL;
                    int w2 = 2 * w + (m >> 9);
                    int ckH = h2 / 3, sD = h2 - ckH * 3;
                    long r = (long)sD * 12288 + (n * 32 + ckH) * 96 + w2;
                    split_g(v, outHi, outLo, r * 512 + (m & 511));
                }
            }
        }
    }
}

// ------------------------- prep kernels -----------------------------------
__global__ void splitW(const float* __restrict__ src, __half* __restrict__ hi,
                       __half* __restrict__ lo, int count) {
    int i = blockIdx.x * 256 + threadIdx.x;
    if (i < count) split_g(src[i], hi, lo, i);
}

// conv weight reorder + split: dst[co*4608 + t*512 + ci]
__global__ void splitWConv(const float* __restrict__ w, __half* __restrict__ hi,
                           __half* __restrict__ lo, int mulL, int mulS) {
    int i = blockIdx.x * 256 + threadIdx.x;
    int ci = i & 511;
    int t = (i >> 9) % 9;
    int co = i / 4608;
    int dl = t / 3, ds = t % 3;
    float v = w[(long)co * 4608 + ci * 9 + dl * mulL + ds * mulS];
    split_g(v, hi, lo, (long)co * 4608 + t * 512 + ci);
}

// x[n,c,h,w] -> B[pix(n,h,w), c] split
__global__ void gatherX(const float* __restrict__ x, __half* __restrict__ bhi,
                        __half* __restrict__ blo) {
    int i = blockIdx.x * 256 + threadIdx.x;
    int c4 = i & 511;
    int pix = i >> 9;
    int n = pix / 2304;
    int p = pix - n * 2304;
    const float* xs = x + ((long)n * 2048 + c4 * 4) * 2304 + p;
    long o = (long)pix * 2048 + c4 * 4;
    split_g(xs[0],    bhi, blo, o + 0);
    split_g(xs[2304], bhi, blo, o + 1);
    split_g(xs[4608], bhi, blo, o + 2);
    split_g(xs[6912], bhi, blo, o + 3);
}

// ---------------------------------------------------------------------------
// kernel_launch.  Inputs: x, w_channel, w_w, w_H, w_lr, b_lr, w_du, b_du
// ---------------------------------------------------------------------------
extern "C" void kernel_launch(void* const* d_in, const int* in_sizes, int n_in,
                              void* d_out, int out_size) {
    const float* x         = (const float*)d_in[0];
    const float* w_channel = (const float*)d_in[1];
    const float* w_w       = (const float*)d_in[2];
    const float* w_H       = (const float*)d_in[3];
    const float* w_lr      = (const float*)d_in[4];
    const float* b_lr      = (const float*)d_in[5];
    const float* w_du      = (const float*)d_in[6];
    const float* b_du      = (const float*)d_in[7];
    float* out = (float*)d_out;

    __half *aHi, *aLo, *bHi, *bLo, *cHi, *cLo, *B2hi, *B2lo;
    __half *wch_hi, *wch_lo, *ww_hi, *ww_lo, *wH_hi, *wH_lo;
    __half *wlr_hi, *wlr_lo, *wdu_hi, *wdu_lo;
    cudaGetSymbolAddress((void**)&aHi, g_aHi);
    cudaGetSymbolAddress((void**)&aLo, g_aLo);
    cudaGetSymbolAddress((void**)&bHi, g_bHi);
    cudaGetSymbolAddress((void**)&bLo, g_bLo);
    cudaGetSymbolAddress((void**)&cHi, g_cHi);
    cudaGetSymbolAddress((void**)&cLo, g_cLo);
    cudaGetSymbolAddress((void**)&B2hi, g_B2hi);
    cudaGetSymbolAddress((void**)&B2lo, g_B2lo);
    cudaGetSymbolAddress((void**)&wch_hi, g_wch_hi);
    cudaGetSymbolAddress((void**)&wch_lo, g_wch_lo);
    cudaGetSymbolAddress((void**)&ww_hi, g_ww_hi);
    cudaGetSymbolAddress((void**)&ww_lo, g_ww_lo);
    cudaGetSymbolAddress((void**)&wH_hi, g_wH_hi);
    cudaGetSymbolAddress((void**)&wH_lo, g_wH_lo);
    cudaGetSymbolAddress((void**)&wlr_hi, g_wlr_hi);
    cudaGetSymbolAddress((void**)&wlr_lo, g_wlr_lo);
    cudaGetSymbolAddress((void**)&wdu_hi, g_wdu_hi);
    cudaGetSymbolAddress((void**)&wdu_lo, g_wdu_lo);

    cudaFuncSetAttribute(gemm_hmma, cudaFuncAttributeMaxDynamicSharedMemorySize,
                         SMEM_TOTAL);

    // weight prep
    splitW<<<(512 * 2048) / 256, 256>>>(w_channel, wch_hi, wch_lo, 512 * 2048);
    splitW<<<(1024 * 512) / 256, 256>>>(w_w, ww_hi, ww_lo, 1024 * 512);
    splitW<<<(1024 * 512) / 256, 256>>>(w_H, wH_hi, wH_lo, 1024 * 512);
    splitWConv<<<(512 * 4608) / 256, 256>>>(w_lr, wlr_hi, wlr_lo, 3, 1);
    splitWConv<<<(512 * 4608) / 256, 256>>>(w_du, wdu_hi, wdu_lo, 1, 3);

    // stage 1: split(x) -> a [9216,2048]; y1 = w_channel @ x -> split B2
    gatherX<<<(9216 * 512) / 256, 256>>>(x, aHi, aLo);
    gemm_hmma<<<dim3(4, 72), 256, SMEM_TOTAL>>>(
        wch_hi, wch_lo, aHi, aLo, 2048, 2048, 0, 0, 1, nullptr,
        nullptr, B2hi, B2lo);

    // stage 2: w_w @ y1, epilogue = H-shuffle -> LR act (s-major) b
    gemm_hmma<<<dim3(8, 72), 256, SMEM_TOTAL>>>(
        ww_hi, ww_lo, B2hi, B2lo, 512, 512, 0, 0, 5, nullptr,
        nullptr, bHi, bLo);

    // convLR pass 1 (S=6144) -> split c
    gemm_hmma<<<dim3(4, 144), 256, SMEM_TOTAL>>>(
        wlr_hi, wlr_lo, bHi, bLo, 4608, 512, 1, 6144, 3, b_lr,
        nullptr, cHi, cLo);

    // convLR pass 2 -> split a
    gemm_hmma<<<dim3(4, 144), 256, SMEM_TOTAL>>>(
        wlr_hi, wlr_lo, cHi, cLo, 4608, 512, 1, 6144, 3, b_lr,
        nullptr, aHi, aLo);

    // w_H stage: epilogue = W-shuffle -> DU act (s-major) b
    gemm_hmma<<<dim3(8, 144), 256, SMEM_TOTAL>>>(
        wH_hi, wH_lo, aHi, aLo, 512, 512, 0, 0, 6, nullptr,
        nullptr, bHi, bLo);

    // convDU pass 1 (S=12288) -> split a
    gemm_hmma<<<dim3(4, 288), 256, SMEM_TOTAL>>>(
        wdu_hi, wdu_lo, bHi, bLo, 4608, 512, 1, 12288, 3, b_du,
        nullptr, aHi, aLo);

    // convDU pass 2 -> final NCHW output
    gemm_hmma<<<dim3(4, 288), 256, SMEM_TOTAL>>>(
        wdu_hi, wdu_lo, aHi, aLo, 4608, 512, 1, 12288, 4, b_du,
        out, nullptr, nullptr);
}

// round 12
// speedup vs baseline: 1.8855x; 1.3536x over previous
#include <cuda_runtime.h>
#include <cuda_fp16.h>
#include <cstdint>

// ===========================================================================
// SSRupsampling via HMMA (mma.sync m16n8k16, fp32 accum), fp16 split.
// 1x1 GEMMs: 3-product (full fp32-grade). Conv GEMMs: 2-product (weight
// hi+lo x act hi) -- act-lo term dropped, ~1.4e-4/stage quantization.
// Conv B = shifted view of S-MAJOR [pix,512] act: r = s*S + img*96 + l;
// uniform s per 128-row N-tile -> invalid-ds taps skipped (22% saved).
// 128x128 block tile, 32x64 warp tile, 256 thr, 2 CTA/SM, swizzled smem,
// 3-stage cp.async, single sync per chunk. Shuffles fused into epilogues.
// ===========================================================================

// ------------------------------ scratch -----------------------------------
__device__ __half g_aHi[36864L * 512], g_aLo[36864L * 512];
__device__ __half g_bHi[36864L * 512], g_bLo[36864L * 512];
__device__ __half g_cHi[18432 * 512],  g_cLo[18432 * 512];
__device__ __half g_B2hi[9216 * 512],  g_B2lo[9216 * 512];
__device__ __half g_wch_hi[512 * 2048], g_wch_lo[512 * 2048];
__device__ __half g_ww_hi[1024 * 512],  g_ww_lo[1024 * 512];
__device__ __half g_wH_hi[1024 * 512],  g_wH_lo[1024 * 512];
__device__ __half g_wlr_hi[512 * 4608], g_wlr_lo[512 * 4608];
__device__ __half g_wdu_hi[512 * 4608], g_wdu_lo[512 * 4608];

// ------------------------------ helpers -----------------------------------
__device__ __forceinline__ uint32_t smem_u32(const void* p) {
    uint32_t a;
    asm("{ .reg .u64 t; cvta.to.shared.u64 t, %1; cvt.u32.u64 %0, t; }"
        : "=r"(a) : "l"(p));
    return a;
}
__device__ __forceinline__ void ldsm_x4(uint32_t* r, uint32_t addr) {
    asm volatile("ldmatrix.sync.aligned.m8n8.x4.shared.b16 {%0,%1,%2,%3}, [%4];"
                 : "=r"(r[0]), "=r"(r[1]), "=r"(r[2]), "=r"(r[3]) : "r"(addr));
}
__device__ __forceinline__ void mma16816(float* c, const uint32_t* a,
                                         const uint32_t* b) {
    asm volatile(
        "mma.sync.aligned.m16n8k16.row.col.f32.f16.f16.f32 "
        "{%0,%1,%2,%3}, {%4,%5,%6,%7}, {%8,%9}, {%0,%1,%2,%3};"
        : "+f"(c[0]), "+f"(c[1]), "+f"(c[2]), "+f"(c[3])
        : "r"(a[0]), "r"(a[1]), "r"(a[2]), "r"(a[3]), "r"(b[0]), "r"(b[1]));
}
__device__ __forceinline__ void cp16(uint32_t sa, const void* ga) {
    asm volatile("cp.async.cg.shared.global [%0], [%1], 16;"
                 :: "r"(sa), "l"(ga));
}
__device__ __forceinline__ void cp16p(uint32_t sa, const void* ga, int sz) {
    asm volatile("cp.async.cg.shared.global [%0], [%1], 16, %2;"
                 :: "r"(sa), "l"(ga), "r"(sz));
}

#define BK 32
#define TILE_BYTES 8192            // 128 rows x 64B, swizzled
#define OFF_AHI 0
#define OFF_ALO TILE_BYTES
#define OFF_BHI (2 * TILE_BYTES)
#define OFF_BLO (3 * TILE_BYTES)
#define STAGE_BYTES (4 * TILE_BYTES)   // 32768
#define NSTAGE 3
#define SMEM_TOTAL (NSTAGE * STAGE_BYTES)   // 98304 per CTA

// swizzled byte offset of the 16B unit (row, lcol), row 0..127, lcol 0..3
__device__ __forceinline__ uint32_t swz(int row, int lcol) {
    return (uint32_t)((row >> 1) * 128 +
                      ((((row & 1) * 4 + lcol) ^ ((row >> 1) & 7)) * 16));
}

// ---------------------------------------------------------------------------
// GEMM: D[m,n] = sum_k A[m,k]*B[n,k], fp16 split, fp32 accum.
// PROD2=0: Ah*Bh + Ah*Bl + Al*Bh (3 products). PROD2=1: Ah*Bh + Al*Bh
// (B-lo never loaded).
// Block tile 128x128, BK=32, 256 threads (8 warps, 4m x 2n), warp 32x64.
// conv!=0: B read from S-MAJOR [Npix,512] act; uniform s per N-tile;
// K-loop covers valid taps only; per-row l-mask in loader.
// Modes: 1 split [pix,512]; 3 conv bias+relu split [pix,512];
//        4 bias+relu NCHW scatter; 5 split + H-shuffle; 6 split + W-shuffle.
// wantLo: write lo half of split outputs (0 when consumer is 2-product).
// ---------------------------------------------------------------------------
template <int PROD2>
__global__ __launch_bounds__(256, 2)
void gemm_hmma(const __half* __restrict__ Ahi, const __half* __restrict__ Alo,
               const __half* __restrict__ Bhi, const __half* __restrict__ Blo,
               int K, int Kb, int conv, int S, int mode, int wantLo,
               const float* __restrict__ bias, float* __restrict__ outF,
               __half* __restrict__ outHi, __half* __restrict__ outLo) {
    extern __shared__ char smem[];
    const uint32_t sb = smem_u32(smem);
    const int tid = threadIdx.x;
    const int lane = tid & 31, wid = tid >> 5;
    const int wm = wid >> 1, wn = wid & 1;
    const int m0 = blockIdx.x * 128;
    const long n0 = (long)blockIdx.y * 128;

    const __half* gA0 = Ahi + (long)m0 * K;
    const __half* gA1 = Alo + (long)m0 * K;
    const __half* gB0 = Bhi + n0 * Kb;
    const __half* gB1 = Blo + n0 * Kb;

    const int lrow0 = tid >> 2, lcol = tid & 3;
    const int lrow1 = lrow0 + 64;
    const uint32_t sw0 = swz(lrow0, lcol);
    const uint32_t sw1 = swz(lrow1, lcol);

    // conv geometry: s uniform per tile; l = r % 96
    int l0 = 0, l1 = 0, nds = 3, dsmin = -1;
    if (conv) {
        const int sTile = (int)(n0 / S);
        l0 = (int)((n0 + lrow0) % 96);
        l1 = (int)((n0 + lrow1) % 96);
        nds = (sTile == 1) ? 3 : 2;
        dsmin = (sTile == 0) ? 0 : -1;
    }

    const int lg = lane >> 3, lr = lane & 7;
    const uint32_t abase = swz(wm * 32 + (lg & 1) * 8 + lr, lg >> 1);
    const uint32_t bbase = swz(wn * 64 + (lg >> 1) * 8 + lr, lg & 1);

    float acc[2][8][4];
    #pragma unroll
    for (int i = 0; i < 2; i++)
        #pragma unroll
        for (int j = 0; j < 8; j++)
            #pragma unroll
            for (int c = 0; c < 4; c++) acc[i][j][c] = 0.f;

    const int nC = conv ? (3 * nds * 16) : (K / BK);

    auto issue = [&](int kc) {
        const uint32_t so = sb + (kc % NSTAGE) * STAGE_BYTES;
        if (conv) {
            const int ti = kc >> 4;
            const int dlm = ti / nds - 1;
            const int dsm = dsmin + ti % nds;
            const int t = (dlm + 1) * 3 + (dsm + 1);
            const int koff = (kc & 15) * 32 + lcol * 8;
            const long ga0 = (long)lrow0 * K + t * 512 + koff;
            const long ga1 = (long)lrow1 * K + t * 512 + koff;
            cp16(so + OFF_AHI + sw0, gA0 + ga0);
            cp16(so + OFF_AHI + sw1, gA0 + ga1);
            cp16(so + OFF_ALO + sw0, gA1 + ga0);
            cp16(so + OFF_ALO + sw1, gA1 + ga1);
            const long rs = (long)(dlm + dsm * S) * Kb;
            const int v0 = ((unsigned)(l0 + dlm) < 96u) ? 16 : 0;
            const int v1 = ((unsigned)(l1 + dlm) < 96u) ? 16 : 0;
            const long gb0 = (long)lrow0 * Kb + rs + koff;
            const long gb1 = (long)lrow1 * Kb + rs + koff;
            cp16p(so + OFF_BHI + sw0, gB0 + gb0, v0);
            cp16p(so + OFF_BHI + sw1, gB0 + gb1, v1);
            if (!PROD2) {
                cp16p(so + OFF_BLO + sw0, gB1 + gb0, v0);
                cp16p(so + OFF_BLO + sw1, gB1 + gb1, v1);
            }
        } else {
            const long kb = (long)kc * BK;
            const long ga0 = (long)lrow0 * K + kb + lcol * 8;
            const long ga1 = (long)lrow1 * K + kb + lcol * 8;
            cp16(so + OFF_AHI + sw0, gA0 + ga0);
            cp16(so + OFF_AHI + sw1, gA0 + ga1);
            cp16(so + OFF_ALO + sw0, gA1 + ga0);
            cp16(so + OFF_ALO + sw1, gA1 + ga1);
            const long gb0 = (long)lrow0 * Kb + kb + lcol * 8;
            const long gb1 = (long)lrow1 * Kb + kb + lcol * 8;
            cp16(so + OFF_BHI + sw0, gB0 + gb0);
            cp16(so + OFF_BHI + sw1, gB0 + gb1);
            if (!PROD2) {
                cp16(so + OFF_BLO + sw0, gB1 + gb0);
                cp16(so + OFF_BLO + sw1, gB1 + gb1);
            }
        }
        asm volatile("cp.async.commit_group;" ::: "memory");
    };

    issue(0);
    issue(1);
    for (int kc = 0; kc < nC; kc++) {
        if (kc + 1 < nC) {
            asm volatile("cp.async.wait_group 1;" ::: "memory");
        } else {
            asm volatile("cp.async.wait_group 0;" ::: "memory");
        }
        __syncthreads();              // kc data visible; kc-1 reads done
        if (kc + 2 < nC) issue(kc + 2);

        const uint32_t so = sb + (kc % NSTAGE) * STAGE_BYTES;
        #pragma unroll
        for (int ks = 0; ks < 2; ks++) {
            const uint32_t axor = ks * 32;
            uint32_t ah[2][4], al[2][4];
            const uint32_t ab = so + OFF_AHI + abase;
            ldsm_x4(ah[0], (ab) ^ axor);
            ldsm_x4(ah[1], (ab + 1024) ^ axor);
            ldsm_x4(al[0], (ab + TILE_BYTES) ^ axor);
            ldsm_x4(al[1], (ab + TILE_BYTES + 1024) ^ axor);
            const uint32_t bb = so + OFF_BHI + bbase;
            #pragma unroll
            for (int p = 0; p < 4; p++) {
                uint32_t bh[4];
                ldsm_x4(bh, (bb + p * 1024) ^ axor);
                if (!PROD2) {
                    uint32_t bl[4];
                    ldsm_x4(bl, (bb + p * 1024 + TILE_BYTES) ^ axor);
                    #pragma unroll
                    for (int mi = 0; mi < 2; mi++) {
                        mma16816(acc[mi][2 * p],     ah[mi], bh);
                        mma16816(acc[mi][2 * p],     ah[mi], bl);
                        mma16816(acc[mi][2 * p],     al[mi], bh);
                        mma16816(acc[mi][2 * p + 1], ah[mi], bh + 2);
                        mma16816(acc[mi][2 * p + 1], ah[mi], bl + 2);
                        mma16816(acc[mi][2 * p + 1], al[mi], bh + 2);
                    }
                } else {
                    #pragma unroll
                    for (int mi = 0; mi < 2; mi++) {
                        mma16816(acc[mi][2 * p],     ah[mi], bh);
                        mma16816(acc[mi][2 * p],     al[mi], bh);
                        mma16816(acc[mi][2 * p + 1], ah[mi], bh + 2);
                        mma16816(acc[mi][2 * p + 1], al[mi], bh + 2);
                    }
                }
            }
        }
    }

    // ---------------- epilogue -------------------------------------------
    const int mrow = m0 + wm * 32 + (lane >> 2);
    const int nrow = wn * 64 + 2 * (lane & 3);
    #pragma unroll
    for (int mi = 0; mi < 2; mi++) {
        #pragma unroll
        for (int nj = 0; nj < 8; nj++) {
            #pragma unroll
            for (int ci = 0; ci < 4; ci++) {
                const int m = mrow + mi * 16 + (ci >> 1) * 8;
                const long pix = n0 + nrow + nj * 8 + (ci & 1);
                float v = acc[mi][nj][ci];
                if (mode == 3 || mode == 4) v = fmaxf(v + bias[m], 0.f);
                long oidx = -1;
                int oc = m;
                if (mode == 1 || mode == 3) {
                    oidx = pix * 512 + m;
                } else if (mode == 4) {
                    // final NCHW scatter from DU s-major rows
                    int p = (int)pix;
                    int sD = p / 12288, rem = p % 12288;
                    int img = rem / 96, w2 = rem % 96;
                    int n = img >> 5, ckH = img & 31;
                    int h = ckH * 3 + sD;
                    outF[(((long)n * 512 + m) * 96 + h) * 96 + w2] = v;
                    continue;
                } else if (mode == 5) {
                    // stage2: H-shuffle -> LR act (s-major)
                    int p = (int)pix;
                    int n = p / 2304, rem = p - n * 2304;
                    int h = rem / 48, w = rem - h * 48;
                    int h2 = 2 * h + (m >> 9);
                    int ckW = w / 3, s = w - ckW * 3;
                    long r = (long)s * 6144 + (n * 16 + ckW) * 96 + h2;
                    oidx = r * 512 + (m & 511);
                    oc = m & 511;
                } else {
                    // mode 6: w_H out -> DU act (s-major)
                    int p = (int)pix;
                    int sL = p / 6144, rem = p % 6144;
                    int img = rem / 96, h2 = rem % 96;
                    int n = img >> 4, ckW = img & 15;
                    int w = ckW * 3 + sL;
                    int w2 = 2 * w + (m >> 9);
                    int ckH = h2 / 3, sD = h2 - ckH * 3;
                    long r = (long)sD * 12288 + (n * 32 + ckH) * 96 + w2;
                    oidx = r * 512 + (m & 511);
                    oc = m & 511;
                }
                __half h = __float2half_rn(v);
                outHi[oidx] = h;
                if (wantLo)
                    outLo[oidx] = __float2half_rn(v - __half2float(h));
                (void)oc;
            }
        }
    }
}

// ------------------------- prep kernels -----------------------------------
__device__ __forceinline__ void split_g(float v, __half* hi, __half* lo,
                                        long idx) {
    __half h = __float2half_rn(v);
    hi[idx] = h;
    lo[idx] = __float2half_rn(v - __half2float(h));
}

__global__ void splitW(const float* __restrict__ src, __half* __restrict__ hi,
                       __half* __restrict__ lo, int count) {
    int i = blockIdx.x * 256 + threadIdx.x;
    if (i < count) split_g(src[i], hi, lo, i);
}

// conv weight reorder + split: dst[co*4608 + t*512 + ci]
__global__ void splitWConv(const float* __restrict__ w, __half* __restrict__ hi,
                           __half* __restrict__ lo, int mulL, int mulS) {
    int i = blockIdx.x * 256 + threadIdx.x;
    int ci = i & 511;
    int t = (i >> 9) % 9;
    int co = i / 4608;
    int dl = t / 3, ds = t % 3;
    float v = w[(long)co * 4608 + ci * 9 + dl * mulL + ds * mulS];
    split_g(v, hi, lo, (long)co * 4608 + t * 512 + ci);
}

// x[n,c,h,w] -> B[pix(n,h,w), c] split
__global__ void gatherX(const float* __restrict__ x, __half* __restrict__ bhi,
                        __half* __restrict__ blo) {
    int i = blockIdx.x * 256 + threadIdx.x;
    int c4 = i & 511;
    int pix = i >> 9;
    int n = pix / 2304;
    int p = pix - n * 2304;
    const float* xs = x + ((long)n * 2048 + c4 * 4) * 2304 + p;
    long o = (long)pix * 2048 + c4 * 4;
    split_g(xs[0],    bhi, blo, o + 0);
    split_g(xs[2304], bhi, blo, o + 1);
    split_g(xs[4608], bhi, blo, o + 2);
    split_g(xs[6912], bhi, blo, o + 3);
}

// ---------------------------------------------------------------------------
// kernel_launch.  Inputs: x, w_channel, w_w, w_H, w_lr, b_lr, w_du, b_du
// ---------------------------------------------------------------------------
extern "C" void kernel_launch(void* const* d_in, const int* in_sizes, int n_in,
                              void* d_out, int out_size) {
    const float* x         = (const float*)d_in[0];
    const float* w_channel = (const float*)d_in[1];
    const float* w_w       = (const float*)d_in[2];
    const float* w_H       = (const float*)d_in[3];
    const float* w_lr      = (const float*)d_in[4];
    const float* b_lr      = (const float*)d_in[5];
    const float* w_du      = (const float*)d_in[6];
    const float* b_du      = (const float*)d_in[7];
    float* out = (float*)d_out;

    __half *aHi, *aLo, *bHi, *bLo, *cHi, *cLo, *B2hi, *B2lo;
    __half *wch_hi, *wch_lo, *ww_hi, *ww_lo, *wH_hi, *wH_lo;
    __half *wlr_hi, *wlr_lo, *wdu_hi, *wdu_lo;
    cudaGetSymbolAddress((void**)&aHi, g_aHi);
    cudaGetSymbolAddress((void**)&aLo, g_aLo);
    cudaGetSymbolAddress((void**)&bHi, g_bHi);
    cudaGetSymbolAddress((void**)&bLo, g_bLo);
    cudaGetSymbolAddress((void**)&cHi, g_cHi);
    cudaGetSymbolAddress((void**)&cLo, g_cLo);
    cudaGetSymbolAddress((void**)&B2hi, g_B2hi);
    cudaGetSymbolAddress((void**)&B2lo, g_B2lo);
    cudaGetSymbolAddress((void**)&wch_hi, g_wch_hi);
    cudaGetSymbolAddress((void**)&wch_lo, g_wch_lo);
    cudaGetSymbolAddress((void**)&ww_hi, g_ww_hi);
    cudaGetSymbolAddress((void**)&ww_lo, g_ww_lo);
    cudaGetSymbolAddress((void**)&wH_hi, g_wH_hi);
    cudaGetSymbolAddress((void**)&wH_lo, g_wH_lo);
    cudaGetSymbolAddress((void**)&wlr_hi, g_wlr_hi);
    cudaGetSymbolAddress((void**)&wlr_lo, g_wlr_lo);
    cudaGetSymbolAddress((void**)&wdu_hi, g_wdu_hi);
    cudaGetSymbolAddress((void**)&wdu_lo, g_wdu_lo);

    cudaFuncSetAttribute(gemm_hmma<0>, cudaFuncAttributeMaxDynamicSharedMemorySize,
                         SMEM_TOTAL);
    cudaFuncSetAttribute(gemm_hmma<1>, cudaFuncAttributeMaxDynamicSharedMemorySize,
                         SMEM_TOTAL);

    // weight prep
    splitW<<<(512 * 2048) / 256, 256>>>(w_channel, wch_hi, wch_lo, 512 * 2048);
    splitW<<<(1024 * 512) / 256, 256>>>(w_w, ww_hi, ww_lo, 1024 * 512);
    splitW<<<(1024 * 512) / 256, 256>>>(w_H, wH_hi, wH_lo, 1024 * 512);
    splitWConv<<<(512 * 4608) / 256, 256>>>(w_lr, wlr_hi, wlr_lo, 3, 1);
    splitWConv<<<(512 * 4608) / 256, 256>>>(w_du, wdu_hi, wdu_lo, 1, 3);

    // stage 1: split(x) -> a [9216,2048]; y1 = w_channel @ x -> split B2
    gatherX<<<(9216 * 512) / 256, 256>>>(x, aHi, aLo);
    gemm_hmma<0><<<dim3(4, 72), 256, SMEM_TOTAL>>>(
        wch_hi, wch_lo, aHi, aLo, 2048, 2048, 0, 0, 1, 1, nullptr,
        nullptr, B2hi, B2lo);

    // stage 2: w_w @ y1, epilogue = H-shuffle -> LR act (s-major, hi only)
    gemm_hmma<0><<<dim3(8, 72), 256, SMEM_TOTAL>>>(
        ww_hi, ww_lo, B2hi, B2lo, 512, 512, 0, 0, 5, 0, nullptr,
        nullptr, bHi, bLo);

    // convLR pass 1 (S=6144, 2-product) -> c hi only
    gemm_hmma<1><<<dim3(4, 144), 256, SMEM_TOTAL>>>(
        wlr_hi, wlr_lo, bHi, bLo, 4608, 512, 1, 6144, 3, 0, b_lr,
        nullptr, cHi, cLo);

    // convLR pass 2 (2-product) -> a hi+lo (feeds 3-product w_H)
    gemm_hmma<1><<<dim3(4, 144), 256, SMEM_TOTAL>>>(
        wlr_hi, wlr_lo, cHi, cLo, 4608, 512, 1, 6144, 3, 1, b_lr,
        nullptr, aHi, aLo);

    // w_H stage (3-product): epilogue = W-shuffle -> DU act (hi only)
    gemm_hmma<0><<<dim3(8, 144), 256, SMEM_TOTAL>>>(
        wH_hi, wH_lo, aHi, aLo, 512, 512, 0, 0, 6, 0, nullptr,
        nullptr, bHi, bLo);

    // convDU pass 1 (S=12288, 2-product) -> a hi only
    gemm_hmma<1><<<dim3(4, 288), 256, SMEM_TOTAL>>>(
        wdu_hi, wdu_lo, bHi, bLo, 4608, 512, 1, 12288, 3, 0, b_du,
        nullptr, aHi, aLo);

    // convDU pass 2 (2-product) -> final NCHW output
    gemm_hmma<1><<<dim3(4, 288), 256, SMEM_TOTAL>>>(
        wdu_hi, wdu_lo, aHi, aLo, 4608, 512, 1, 12288, 4, 0, b_du,
        out, nullptr, nullptr);
}